// round 10
// baseline (speedup 1.0000x reference)
#include <cuda_runtime.h>
#include <cuda_fp16.h>
#include <cstdint>

// ======================= problem constants =======================
#define MDIM 32768      // B*S = 16*2048
#define NDIM 4096       // out features
#define KDIM 1024       // in features
#define NBATCH 16

#define BM 128
#define BN 128
#define BK 64                 // halves per K-slab = one SW128 tile col-block
#define NKT 16                // K tiles
#define STAGES 2

#define TILEB  16384                // one 128x64-half tile, swizzled, contiguous
#define STAGEB (3 * TILEB)          // A + W + G = 49152
#define SMEM_STAGE0 1024
#define SMEMB  (SMEM_STAGE0 + STAGES * STAGEB)   // 99328 -> 2 CTAs/SM

// barrier smem offsets
#define OFF_FULL  0      // 2 x 8B
#define OFF_EMPTY 64     // 2 x 8B

// pre-kernel grid split
#define X_TILES   (MDIM / BM * NKT)                // 4096 tiles
#define X_BLOCKS  ((size_t)X_TILES * 1024 / 256)   // 16384
#define W_TILES   (NDIM / BN * NKT)                // 512 tiles
#define W_BLOCKS  ((size_t)W_TILES * 1024 / 256)   // 2048

// ======================= static fp16 scratch: TILED + PRE-SWIZZLED =======================
__device__ __align__(1024) unsigned char g_xh[(size_t)MDIM * KDIM * 2];   // 64 MB
__device__ __align__(1024) unsigned char g_wh[(size_t)NDIM * KDIM * 2];   // 8 MB (W fp16)
__device__ __align__(1024) unsigned char g_gh[(size_t)NDIM * KDIM * 2];   // 8 MB (G fp16)

// ======================= small helpers =======================
__device__ __forceinline__ uint32_t h2_as_u32(__half2 h) {
    return *reinterpret_cast<uint32_t*>(&h);
}
__device__ __forceinline__ __half2 u32_as_h2(uint32_t u) {
    return *reinterpret_cast<__half2*>(&u);
}

__device__ __forceinline__ uint32_t smem_u32(const void* p) {
    uint32_t a;
    asm("{ .reg .u64 t; cvta.to.shared.u64 t, %1; cvt.u32.u64 %0, t; }" : "=r"(a) : "l"(p));
    return a;
}

#define SW128(o) ((o) ^ (((o) >> 3) & 0x70))

__device__ __forceinline__ void mbar_init(uint32_t bar, uint32_t cnt) {
    asm volatile("mbarrier.init.shared.b64 [%0], %1;" :: "r"(bar), "r"(cnt) : "memory");
}
__device__ __forceinline__ void mbar_arrive(uint32_t bar) {
    asm volatile("mbarrier.arrive.shared.b64 _, [%0];" :: "r"(bar) : "memory");
}
__device__ __forceinline__ void mbar_expect_tx(uint32_t bar, uint32_t bytes) {
    asm volatile("mbarrier.arrive.expect_tx.shared.b64 _, [%0], %1;" :: "r"(bar), "r"(bytes) : "memory");
}
__device__ __forceinline__ void mbar_wait(uint32_t bar, uint32_t parity) {
    asm volatile(
        "{\n\t"
        ".reg .pred P;\n\t"
        "WL_%=:\n\t"
        "mbarrier.try_wait.parity.acquire.cta.shared::cta.b64 P, [%0], %1, 0x989680;\n\t"
        "@P bra.uni WD_%=;\n\t"
        "bra.uni WL_%=;\n\t"
        "WD_%=:\n\t"
        "}"
        :: "r"(bar), "r"(parity) : "memory");
}
// 1D bulk async copy global->shared, completes via mbarrier tx (sm_90 baseline PTX)
__device__ __forceinline__ void bulk_g2s(uint32_t dst, const void* src, uint32_t bytes, uint32_t bar) {
    asm volatile(
        "cp.async.bulk.shared::cluster.global.mbarrier::complete_tx::bytes [%0], [%1], %2, [%3];"
        :: "r"(dst), "l"(src), "r"(bytes), "r"(bar) : "memory");
}

__device__ __forceinline__ void ldsm4(uint32_t* d, uint32_t addr) {
    asm volatile("ldmatrix.sync.aligned.m8n8.x4.shared.b16 {%0,%1,%2,%3}, [%4];"
                 : "=r"(d[0]), "=r"(d[1]), "=r"(d[2]), "=r"(d[3]) : "r"(addr));
}

__device__ __forceinline__ void mma16816(float* c, const uint32_t* a, uint32_t b0, uint32_t b1) {
    asm volatile(
        "mma.sync.aligned.m16n8k16.row.col.f32.f16.f16.f32 "
        "{%0,%1,%2,%3}, {%4,%5,%6,%7}, {%8,%9}, {%0,%1,%2,%3};"
        : "+f"(c[0]), "+f"(c[1]), "+f"(c[2]), "+f"(c[3])
        : "r"(a[0]), "r"(a[1]), "r"(a[2]), "r"(a[3]), "r"(b0), "r"(b1));
}

__device__ __forceinline__ void stg_cs_v2(float* p, float2 v) {
    asm volatile("st.global.cs.v2.f32 [%0], {%1, %2};" :: "l"(p), "f"(v.x), "f"(v.y) : "memory");
}

// ======================= fused pre-pass: convert + tile + swizzle =======================
// part 1 (blocks [0, X_BLOCKS)):         x fp32 -> g_xh fp16 tiled-swizzled
// part 2 (blocks [X_BLOCKS, +W_BLOCKS)): W, G fp32 -> g_wh, g_gh fp16 tiled-swizzled
__global__ void __launch_bounds__(256) pre_kernel(const float* __restrict__ x,
                                                  const float* __restrict__ w,
                                                  const float* __restrict__ g) {
    const int tid = threadIdx.x;
    if (blockIdx.x < X_BLOCKS) {
        size_t cid = (size_t)blockIdx.x * 256 + tid;       // 16B chunk id
        size_t tileIdx = cid >> 10;                        // 1024 chunks per tile
        int t  = (int)(cid & 1023);
        int r  = t >> 3, cc = t & 7;
        int mb = (int)(tileIdx >> 4), kt = (int)(tileIdx & 15);
        const float* src = x + ((size_t)mb * 128 + r) * KDIM + kt * 64 + cc * 8;
        float4 v0 = *reinterpret_cast<const float4*>(src);
        float4 v1 = *reinterpret_cast<const float4*>(src + 4);
        uint4 o;
        o.x = h2_as_u32(__floats2half2_rn(v0.x, v0.y));
        o.y = h2_as_u32(__floats2half2_rn(v0.z, v0.w));
        o.z = h2_as_u32(__floats2half2_rn(v1.x, v1.y));
        o.w = h2_as_u32(__floats2half2_rn(v1.z, v1.w));
        *reinterpret_cast<uint4*>(g_xh + tileIdx * TILEB + SW128(r * 128 + cc * 16)) = o;
    } else {
        size_t cid = (size_t)(blockIdx.x - X_BLOCKS) * 256 + tid;
        size_t tileIdx = cid >> 10;                                  // 0..511
        int t  = (int)(cid & 1023);
        int r  = t >> 3, cc = t & 7;
        int nb = (int)(tileIdx >> 4), kt = (int)(tileIdx & 15);
        const size_t soff = ((size_t)nb * 128 + r) * KDIM + kt * 64 + cc * 8;
        float4 vw0 = *reinterpret_cast<const float4*>(w + soff);
        float4 vw1 = *reinterpret_cast<const float4*>(w + soff + 4);
        float4 vg0 = *reinterpret_cast<const float4*>(g + soff);
        float4 vg1 = *reinterpret_cast<const float4*>(g + soff + 4);
        const uint32_t swoff = SW128(r * 128 + cc * 16);
        uint4 ow, og;
        ow.x = h2_as_u32(__floats2half2_rn(vw0.x, vw0.y));
        ow.y = h2_as_u32(__floats2half2_rn(vw0.z, vw0.w));
        ow.z = h2_as_u32(__floats2half2_rn(vw1.x, vw1.y));
        ow.w = h2_as_u32(__floats2half2_rn(vw1.z, vw1.w));
        og.x = h2_as_u32(__floats2half2_rn(vg0.x, vg0.y));
        og.y = h2_as_u32(__floats2half2_rn(vg0.z, vg0.w));
        og.z = h2_as_u32(__floats2half2_rn(vg1.x, vg1.y));
        og.w = h2_as_u32(__floats2half2_rn(vg1.z, vg1.w));
        *reinterpret_cast<uint4*>(g_wh + tileIdx * TILEB + swoff) = ow;
        *reinterpret_cast<uint4*>(g_gh + tileIdx * TILEB + swoff) = og;
    }
}

// ======================= GEMM kernel =======================
// 128 threads = 4 warps (2x2), warp tile 64x64, mma m16n8k16 (the proven R6 consumer).
// B-side combined in registers: bc = W - lr*G via HFMA2, after ldsm of W & G frags.
// 2-stage pipeline, stage = A + W + G (48KB), fills via cp.async.bulk (tid 0).
__global__ void __launch_bounds__(128, 2) gemm_kernel(const float* __restrict__ bias,
                                                      const float* __restrict__ gbias,
                                                      const float* __restrict__ lr_arr,
                                                      float* __restrict__ out) {
    extern __shared__ char smem[];
    const uint32_t sb = smem_u32(smem);
    const int tid  = threadIdx.x;
    const int warp = tid >> 5, lane = tid & 31;
    const int warp_m = (warp & 1) * 64;
    const int warp_n = (warp >> 1) * 64;

    const int mb    = blockIdx.y;          // 0..255
    const int nb    = blockIdx.x;          // 0..31
    const int rowA0 = mb * BM;
    const int colB0 = nb * BN;

    const unsigned char* Abase = g_xh + (size_t)(mb * NKT) * TILEB;
    const unsigned char* Wbase = g_wh + (size_t)(nb * NKT) * TILEB;
    const unsigned char* Gbase = g_gh + (size_t)(nb * NKT) * TILEB;

    const float lr = __ldg(lr_arr + (mb >> 4));
    const __half2 nlr2 = __float2half2_rn(-lr);

    const uint32_t full_b  = sb + OFF_FULL;
    const uint32_t empty_b = sb + OFF_EMPTY;

    if (tid == 0) {
        #pragma unroll
        for (int s = 0; s < STAGES; ++s) {
            mbar_init(full_b + s * 8, 1);
            mbar_init(empty_b + s * 8, 128);
        }
    }
    __syncthreads();

    // prologue: tid 0 fills both stages (kt = 0, 1)
    if (tid == 0) {
        #pragma unroll
        for (int p = 0; p < STAGES; ++p) {
            const uint32_t dst = sb + SMEM_STAGE0 + p * STAGEB;
            mbar_expect_tx(full_b + p * 8, STAGEB);
            bulk_g2s(dst,             Abase + (size_t)p * TILEB, TILEB, full_b + p * 8);
            bulk_g2s(dst + TILEB,     Wbase + (size_t)p * TILEB, TILEB, full_b + p * 8);
            bulk_g2s(dst + 2 * TILEB, Gbase + (size_t)p * TILEB, TILEB, full_b + p * 8);
        }
    }

    // ldsm lane addressing (stage-relative, swizzled) — exact R6
    const int a_row  = warp_m + (lane & 15);
    const int a_colb = (lane >> 4) * 16;
    const int b_row  = warp_n + ((lane >> 4) * 8 + (lane & 7));
    const int b_colb = ((lane >> 3) & 1) * 16;

    float acc[4][8][4];
    #pragma unroll
    for (int i = 0; i < 4; ++i)
        #pragma unroll
        for (int j = 0; j < 8; ++j)
            #pragma unroll
            for (int t = 0; t < 4; ++t) acc[i][j][t] = 0.0f;

    uint32_t afr[2][4][4], bc[2][4][4];

    for (int kt = 0; kt < NKT; ++kt) {
        const int s = kt & 1;
        const uint32_t phase = (uint32_t)((kt >> 1) & 1);
        mbar_wait(full_b + s * 8, phase);

        const uint32_t Ab = sb + SMEM_STAGE0 + s * STAGEB;
        const uint32_t Wb = Ab + TILEB;
        const uint32_t Gb = Ab + 2 * TILEB;

        // prime fragments for ks = 0: A ldsm + (W,G ldsm -> combine)
        #pragma unroll
        for (int mf = 0; mf < 4; ++mf)
            ldsm4(afr[0][mf], Ab + SW128((a_row + mf * 16) * 128 + a_colb));
        {
            uint32_t bw[4][4], bg[4][4];
            #pragma unroll
            for (int np = 0; np < 4; ++np) {
                ldsm4(bw[np], Wb + SW128((b_row + np * 16) * 128 + b_colb));
                ldsm4(bg[np], Gb + SW128((b_row + np * 16) * 128 + b_colb));
            }
            #pragma unroll
            for (int np = 0; np < 4; ++np)
                #pragma unroll
                for (int i = 0; i < 4; ++i)
                    bc[0][np][i] = h2_as_u32(__hfma2(u32_as_h2(bg[np][i]), nlr2,
                                                     u32_as_h2(bw[np][i])));
        }

        #pragma unroll
        for (int ks = 0; ks < 4; ++ks) {
            const int cur = ks & 1, nxtb = cur ^ 1;
            uint32_t bw[4][4], bg[4][4];
            if (ks < 3) {
                const int kb = (ks + 1) * 32;
                #pragma unroll
                for (int mf = 0; mf < 4; ++mf)
                    ldsm4(afr[nxtb][mf], Ab + SW128((a_row + mf * 16) * 128 + kb + a_colb));
                #pragma unroll
                for (int np = 0; np < 4; ++np) {
                    ldsm4(bw[np], Wb + SW128((b_row + np * 16) * 128 + kb + b_colb));
                    ldsm4(bg[np], Gb + SW128((b_row + np * 16) * 128 + kb + b_colb));
                }
            }
            // 32 mma on current combined buffers (covers the ldsm latency above)
            #pragma unroll
            for (int mf = 0; mf < 4; ++mf) {
                #pragma unroll
                for (int np = 0; np < 4; ++np) {
                    mma16816(acc[mf][2 * np],     afr[cur][mf], bc[cur][np][0], bc[cur][np][1]);
                    mma16816(acc[mf][2 * np + 1], afr[cur][mf], bc[cur][np][2], bc[cur][np][3]);
                }
            }
            // combine next ks after the mma block (ldsm results ready now)
            if (ks < 3) {
                #pragma unroll
                for (int np = 0; np < 4; ++np)
                    #pragma unroll
                    for (int i = 0; i < 4; ++i)
                        bc[nxtb][np][i] = h2_as_u32(__hfma2(u32_as_h2(bg[np][i]), nlr2,
                                                            u32_as_h2(bw[np][i])));
            }
        }

        // release stage; tid 0 refills it for kt+2
        mbar_arrive(empty_b + s * 8);
        const int nx = kt + STAGES;
        if (tid == 0 && nx < NKT) {
            mbar_wait(empty_b + s * 8, phase);
            const uint32_t dst = sb + SMEM_STAGE0 + s * STAGEB;
            mbar_expect_tx(full_b + s * 8, STAGEB);
            bulk_g2s(dst,             Abase + (size_t)nx * TILEB, TILEB, full_b + s * 8);
            bulk_g2s(dst + TILEB,     Wbase + (size_t)nx * TILEB, TILEB, full_b + s * 8);
            bulk_g2s(dst + 2 * TILEB, Gbase + (size_t)nx * TILEB, TILEB, full_b + s * 8);
        }
    }

    // ---------- epilogue (exact R6 pattern, streaming stores) ----------
    __syncthreads();
    float* bias_s = reinterpret_cast<float*>(smem + SMEM_STAGE0);
    float* gb_s   = bias_s + BN;
    bias_s[tid] = bias[colB0 + tid];        // 128 threads == BN
    gb_s[tid]   = gbias[colB0 + tid];
    __syncthreads();

    #pragma unroll
    for (int mf = 0; mf < 4; ++mf) {
        const int gr0 = rowA0 + warp_m + mf * 16 + (lane >> 2);
        #pragma unroll
        for (int nf = 0; nf < 8; ++nf) {
            const int cl = warp_n + nf * 8 + (lane & 3) * 2;
            const float bc0 = bias_s[cl]     - lr * gb_s[cl];
            const float bc1 = bias_s[cl + 1] - lr * gb_s[cl + 1];
            float2 v0 = make_float2(acc[mf][nf][0] + bc0, acc[mf][nf][1] + bc1);
            float2 v1 = make_float2(acc[mf][nf][2] + bc0, acc[mf][nf][3] + bc1);
            stg_cs_v2(out + (size_t)gr0 * NDIM + colB0 + cl,       v0);
            stg_cs_v2(out + (size_t)(gr0 + 8) * NDIM + colB0 + cl, v1);
        }
    }
}

// ======================= launch =======================
extern "C" void kernel_launch(void* const* d_in, const int* in_sizes, int n_in,
                              void* d_out, int out_size) {
    (void)in_sizes; (void)n_in; (void)out_size;
    const float* x    = (const float*)d_in[0];
    const float* w    = (const float*)d_in[1];
    const float* bias = (const float*)d_in[2];
    const float* g    = (const float*)d_in[3];
    const float* gb   = (const float*)d_in[4];
    const float* lr   = (const float*)d_in[5];
    float* out = (float*)d_out;

    static bool attr_set = false;
    if (!attr_set) {
        cudaFuncSetAttribute(gemm_kernel, cudaFuncAttributeMaxDynamicSharedMemorySize, SMEMB);
        attr_set = true;
    }

    pre_kernel<<<(unsigned)(X_BLOCKS + W_BLOCKS), 256>>>(x, w, g);

    dim3 grid(NDIM / BN, MDIM / BM);   // (32, 256): N fastest for A-tile L2 reuse
    gemm_kernel<<<grid, 128, SMEMB>>>(bias, gb, lr, out);
}

// round 11
// speedup vs baseline: 1.0593x; 1.0593x over previous
#include <cuda_runtime.h>
#include <cuda_fp16.h>
#include <cstdint>

// ======================= problem constants =======================
#define MDIM 32768      // B*S = 16*2048
#define NDIM 4096       // out features
#define KDIM 1024       // in features
#define NBATCH 16

#define BM 128
#define BN 128
#define BK 64                 // halves per K-slab = one SW128 tile col-block
#define NKT (KDIM / BK)       // 16
#define STAGES 3

#define TILEB  16384                // one 128x64-half tile, swizzled, contiguous
#define STAGEB (2 * TILEB)          // A + B = 32768
#define SMEM_STAGE0 1024
#define SMEMB  (SMEM_STAGE0 + STAGES * STAGEB)   // 99328 -> 2 CTAs/SM

// barrier smem offsets
#define OFF_FULL  0      // 3 x 8B
#define OFF_EMPTY 64     // 3 x 8B

// pre-kernel grid split
#define X_TILES   (MDIM / BM * NKT)                // 4096 tiles
#define X_BLOCKS  ((size_t)X_TILES * 1024 / 256)   // 16384
#define W_TILES   (NDIM / BN * NKT)                // 512 tiles per batch
#define W_BLOCKS  ((size_t)W_TILES * 1024 / 256)   // 2048

// ======================= static fp16 scratch: TILED + PRE-SWIZZLED =======================
__device__ __align__(1024) unsigned char g_xh[(size_t)MDIM * KDIM * 2];              // 64 MB
__device__ __align__(1024) unsigned char g_wc[(size_t)NBATCH * NDIM * KDIM * 2];     // 128 MB

// ======================= small helpers =======================
__device__ __forceinline__ uint32_t h2_as_u32(__half2 h) {
    return *reinterpret_cast<uint32_t*>(&h);
}

__device__ __forceinline__ uint32_t smem_u32(const void* p) {
    uint32_t a;
    asm("{ .reg .u64 t; cvta.to.shared.u64 t, %1; cvt.u32.u64 %0, t; }" : "=r"(a) : "l"(p));
    return a;
}

#define SW128(o) ((o) ^ (((o) >> 3) & 0x70))

__device__ __forceinline__ void mbar_init(uint32_t bar, uint32_t cnt) {
    asm volatile("mbarrier.init.shared.b64 [%0], %1;" :: "r"(bar), "r"(cnt) : "memory");
}
__device__ __forceinline__ void mbar_arrive(uint32_t bar) {
    asm volatile("mbarrier.arrive.shared.b64 _, [%0];" :: "r"(bar) : "memory");
}
__device__ __forceinline__ void mbar_expect_tx(uint32_t bar, uint32_t bytes) {
    asm volatile("mbarrier.arrive.expect_tx.shared.b64 _, [%0], %1;" :: "r"(bar), "r"(bytes) : "memory");
}
__device__ __forceinline__ void mbar_wait(uint32_t bar, uint32_t parity) {
    asm volatile(
        "{\n\t"
        ".reg .pred P;\n\t"
        "WL_%=:\n\t"
        "mbarrier.try_wait.parity.acquire.cta.shared::cta.b64 P, [%0], %1, 0x989680;\n\t"
        "@P bra.uni WD_%=;\n\t"
        "bra.uni WL_%=;\n\t"
        "WD_%=:\n\t"
        "}"
        :: "r"(bar), "r"(parity) : "memory");
}
// 1D bulk async copy global->shared, completes via mbarrier tx (sm_90 baseline PTX)
__device__ __forceinline__ void bulk_g2s(uint32_t dst, const void* src, uint32_t bytes, uint32_t bar) {
    asm volatile(
        "cp.async.bulk.shared::cluster.global.mbarrier::complete_tx::bytes [%0], [%1], %2, [%3];"
        :: "r"(dst), "l"(src), "r"(bytes), "r"(bar) : "memory");
}

__device__ __forceinline__ void ldsm4(uint32_t* d, uint32_t addr) {
    asm volatile("ldmatrix.sync.aligned.m8n8.x4.shared.b16 {%0,%1,%2,%3}, [%4];"
                 : "=r"(d[0]), "=r"(d[1]), "=r"(d[2]), "=r"(d[3]) : "r"(addr));
}

__device__ __forceinline__ void mma16816(float* c, const uint32_t* a, uint32_t b0, uint32_t b1) {
    asm volatile(
        "mma.sync.aligned.m16n8k16.row.col.f32.f16.f16.f32 "
        "{%0,%1,%2,%3}, {%4,%5,%6,%7}, {%8,%9}, {%0,%1,%2,%3};"
        : "+f"(c[0]), "+f"(c[1]), "+f"(c[2]), "+f"(c[3])
        : "r"(a[0]), "r"(a[1]), "r"(a[2]), "r"(a[3]), "r"(b0), "r"(b1));
}

__device__ __forceinline__ void stg_cs_v2(float* p, float2 v) {
    asm volatile("st.global.cs.v2.f32 [%0], {%1, %2};" :: "l"(p), "f"(v.x), "f"(v.y) : "memory");
}

// ======================= fused pre-pass: convert + tile + swizzle (proven R6) =======================
__global__ void __launch_bounds__(256) pre_kernel(const float* __restrict__ x,
                                                  const float* __restrict__ w,
                                                  const float* __restrict__ g,
                                                  const float* __restrict__ lr) {
    const int tid = threadIdx.x;
    if (blockIdx.x < X_BLOCKS) {
        size_t cid = (size_t)blockIdx.x * 256 + tid;       // 16B chunk id
        size_t tileIdx = cid >> 10;                        // 1024 chunks per tile
        int t  = (int)(cid & 1023);
        int r  = t >> 3, cc = t & 7;
        int mb = (int)(tileIdx >> 4), kt = (int)(tileIdx & 15);
        const float* src = x + ((size_t)mb * 128 + r) * KDIM + kt * 64 + cc * 8;
        float4 v0 = *reinterpret_cast<const float4*>(src);
        float4 v1 = *reinterpret_cast<const float4*>(src + 4);
        uint4 o;
        o.x = h2_as_u32(__floats2half2_rn(v0.x, v0.y));
        o.y = h2_as_u32(__floats2half2_rn(v0.z, v0.w));
        o.z = h2_as_u32(__floats2half2_rn(v1.x, v1.y));
        o.w = h2_as_u32(__floats2half2_rn(v1.z, v1.w));
        *reinterpret_cast<uint4*>(g_xh + tileIdx * TILEB + SW128(r * 128 + cc * 16)) = o;
    } else {
        size_t cid = (size_t)(blockIdx.x - X_BLOCKS) * 256 + tid;
        size_t tileIdx = cid >> 10;                                  // 0..511
        int t  = (int)(cid & 1023);
        int r  = t >> 3, cc = t & 7;
        int nb = (int)(tileIdx >> 4), kt = (int)(tileIdx & 15);
        const size_t soff = ((size_t)nb * 128 + r) * KDIM + kt * 64 + cc * 8;
        float4 vw0 = *reinterpret_cast<const float4*>(w + soff);
        float4 vw1 = *reinterpret_cast<const float4*>(w + soff + 4);
        float4 vg0 = *reinterpret_cast<const float4*>(g + soff);
        float4 vg1 = *reinterpret_cast<const float4*>(g + soff + 4);
        const uint32_t swoff = SW128(r * 128 + cc * 16);
        #pragma unroll
        for (int b = 0; b < NBATCH; ++b) {
            float l = __ldg(lr + b);
            uint4 o;
            o.x = h2_as_u32(__floats2half2_rn(vw0.x - l * vg0.x, vw0.y - l * vg0.y));
            o.y = h2_as_u32(__floats2half2_rn(vw0.z - l * vg0.z, vw0.w - l * vg0.w));
            o.z = h2_as_u32(__floats2half2_rn(vw1.x - l * vg1.x, vw1.y - l * vg1.y));
            o.w = h2_as_u32(__floats2half2_rn(vw1.z - l * vg1.z, vw1.w - l * vg1.w));
            *reinterpret_cast<uint4*>(g_wc + ((size_t)b * W_TILES + tileIdx) * TILEB + swoff) = o;
        }
    }
}

// ======================= GEMM kernel (exact R6 mainloop) =======================
// 128 threads = 4 warps (2x2), warp tile 64x64, mma m16n8k16.
// Stage fill = 2 x cp.async.bulk (16KB each) from pre-swizzled tiles, tid 0 only.
__global__ void __launch_bounds__(128, 2) gemm_kernel(const float* __restrict__ bias,
                                                      const float* __restrict__ gbias,
                                                      const float* __restrict__ lr_arr,
                                                      float* __restrict__ out) {
    extern __shared__ char smem[];
    const uint32_t sb = smem_u32(smem);
    const int tid  = threadIdx.x;
    const int warp = tid >> 5, lane = tid & 31;
    const int warp_m = (warp & 1) * 64;
    const int warp_n = (warp >> 1) * 64;

    const int mb    = blockIdx.y;          // 0..255
    const int nb    = blockIdx.x;          // 0..31
    const int batch = mb >> 4;
    const int rowA0 = mb * BM;
    const int colB0 = nb * BN;

    const unsigned char* Abase = g_xh + (size_t)(mb * NKT) * TILEB;
    const unsigned char* Bbase = g_wc + ((size_t)batch * W_TILES + nb * NKT) * TILEB;

    const uint32_t full_b  = sb + OFF_FULL;
    const uint32_t empty_b = sb + OFF_EMPTY;

    if (tid == 0) {
        #pragma unroll
        for (int s = 0; s < STAGES; ++s) {
            mbar_init(full_b + s * 8, 1);
            mbar_init(empty_b + s * 8, 128);
        }
    }
    __syncthreads();

    // prologue: tid 0 fills all 3 stages
    if (tid == 0) {
        #pragma unroll
        for (int p = 0; p < STAGES; ++p) {
            const uint32_t dst = sb + SMEM_STAGE0 + p * STAGEB;
            mbar_expect_tx(full_b + p * 8, STAGEB);
            bulk_g2s(dst,         Abase + (size_t)p * TILEB, TILEB, full_b + p * 8);
            bulk_g2s(dst + TILEB, Bbase + (size_t)p * TILEB, TILEB, full_b + p * 8);
        }
    }

    // ldsm lane addressing (stage-relative, swizzled)
    const int a_row  = warp_m + (lane & 15);
    const int a_colb = (lane >> 4) * 16;
    const int b_row  = warp_n + ((lane >> 4) * 8 + (lane & 7));
    const int b_colb = ((lane >> 3) & 1) * 16;

    float acc[4][8][4];
    #pragma unroll
    for (int i = 0; i < 4; ++i)
        #pragma unroll
        for (int j = 0; j < 8; ++j)
            #pragma unroll
            for (int t = 0; t < 4; ++t) acc[i][j][t] = 0.0f;

    uint32_t afr[2][4][4], bfr[2][4][4];

    for (int kt = 0; kt < NKT; ++kt) {
        const int s = kt % STAGES;
        const uint32_t phase = (uint32_t)((kt / STAGES) & 1);
        mbar_wait(full_b + s * 8, phase);

        const uint32_t Ab = sb + SMEM_STAGE0 + s * STAGEB;
        const uint32_t Bb = Ab + TILEB;

        // prime fragments for ks = 0
        #pragma unroll
        for (int mf = 0; mf < 4; ++mf)
            ldsm4(afr[0][mf], Ab + SW128((a_row + mf * 16) * 128 + a_colb));
        #pragma unroll
        for (int np = 0; np < 4; ++np)
            ldsm4(bfr[0][np], Bb + SW128((b_row + np * 16) * 128 + b_colb));

        #pragma unroll
        for (int ks = 0; ks < 4; ++ks) {
            const int cur = ks & 1, nxtb = cur ^ 1;
            if (ks < 3) {
                const int kb = (ks + 1) * 32;
                #pragma unroll
                for (int mf = 0; mf < 4; ++mf)
                    ldsm4(afr[nxtb][mf], Ab + SW128((a_row + mf * 16) * 128 + kb + a_colb));
                #pragma unroll
                for (int np = 0; np < 4; ++np)
                    ldsm4(bfr[nxtb][np], Bb + SW128((b_row + np * 16) * 128 + kb + b_colb));
            }
            #pragma unroll
            for (int mf = 0; mf < 4; ++mf) {
                #pragma unroll
                for (int np = 0; np < 4; ++np) {
                    mma16816(acc[mf][2 * np],     afr[cur][mf], bfr[cur][np][0], bfr[cur][np][1]);
                    mma16816(acc[mf][2 * np + 1], afr[cur][mf], bfr[cur][np][2], bfr[cur][np][3]);
                }
            }
        }

        // release stage; tid 0 refills it for kt+3 once everyone arrived
        mbar_arrive(empty_b + s * 8);
        const int nx = kt + STAGES;
        if (tid == 0 && nx < NKT) {
            mbar_wait(empty_b + s * 8, phase);
            const uint32_t dst = sb + SMEM_STAGE0 + s * STAGEB;
            mbar_expect_tx(full_b + s * 8, STAGEB);
            bulk_g2s(dst,         Abase + (size_t)nx * TILEB, TILEB, full_b + s * 8);
            bulk_g2s(dst + TILEB, Bbase + (size_t)nx * TILEB, TILEB, full_b + s * 8);
        }
    }

    // ---------- epilogue (R6 pattern; streaming stores) ----------
    __syncthreads();
    float* bias_s = reinterpret_cast<float*>(smem + SMEM_STAGE0);
    float* gb_s   = bias_s + BN;
    bias_s[tid] = bias[colB0 + tid];        // 128 threads == BN
    gb_s[tid]   = gbias[colB0 + tid];
    __syncthreads();

    const float lr = __ldg(lr_arr + batch);

    #pragma unroll
    for (int mf = 0; mf < 4; ++mf) {
        const int gr0 = rowA0 + warp_m + mf * 16 + (lane >> 2);
        #pragma unroll
        for (int nf = 0; nf < 8; ++nf) {
            const int cl = warp_n + nf * 8 + (lane & 3) * 2;
            const float bc0 = bias_s[cl]     - lr * gb_s[cl];
            const float bc1 = bias_s[cl + 1] - lr * gb_s[cl + 1];
            float2 v0 = make_float2(acc[mf][nf][0] + bc0, acc[mf][nf][1] + bc1);
            float2 v1 = make_float2(acc[mf][nf][2] + bc0, acc[mf][nf][3] + bc1);
            stg_cs_v2(out + (size_t)gr0 * NDIM + colB0 + cl,       v0);
            stg_cs_v2(out + (size_t)(gr0 + 8) * NDIM + colB0 + cl, v1);
        }
    }
}

// ======================= launch =======================
extern "C" void kernel_launch(void* const* d_in, const int* in_sizes, int n_in,
                              void* d_out, int out_size) {
    (void)in_sizes; (void)n_in; (void)out_size;
    const float* x    = (const float*)d_in[0];
    const float* w    = (const float*)d_in[1];
    const float* bias = (const float*)d_in[2];
    const float* g    = (const float*)d_in[3];
    const float* gb   = (const float*)d_in[4];
    const float* lr   = (const float*)d_in[5];
    float* out = (float*)d_out;

    static bool attr_set = false;
    if (!attr_set) {
        cudaFuncSetAttribute(gemm_kernel, cudaFuncAttributeMaxDynamicSharedMemorySize, SMEMB);
        attr_set = true;
    }

    pre_kernel<<<(unsigned)(X_BLOCKS + W_BLOCKS), 256>>>(x, w, g, lr);

    dim3 grid(NDIM / BN, MDIM / BM);   // (32, 256): N fastest for A-tile L2 reuse
    gemm_kernel<<<grid, 128, SMEMB>>>(bias, gb, lr, out);
}

// round 12
// speedup vs baseline: 1.0868x; 1.0259x over previous
#include <cuda_runtime.h>
#include <cuda_fp16.h>
#include <cstdint>

// ======================= problem constants =======================
#define MDIM 32768      // B*S = 16*2048
#define NDIM 4096       // out features
#define KDIM 1024       // in features
#define NBATCH 16

#define BM 128
#define BN 128
#define BK 64                 // halves per K-slab = one SW128 tile col-block
#define NKT (KDIM / BK)       // 16
#define STAGES 3

#define TILEB  16384                // one 128x64-half tile, swizzled, contiguous
#define STAGEB (2 * TILEB)          // A + B = 32768
#define SMEM_STAGE0 1024
#define SMEMB  (SMEM_STAGE0 + STAGES * STAGEB)   // 99328 -> 2 CTAs/SM

// barrier smem offsets
#define OFF_FULL  0      // 3 x 8B
#define OFF_EMPTY 64     // 3 x 8B

// pre-kernel grid split
#define X_TILES   (MDIM / BM * NKT)                // 4096 tiles
#define X_BLOCKS  ((size_t)X_TILES * 1024 / 256)   // 16384
#define W_TILES   (NDIM / BN * NKT)                // 512 tiles per batch
#define W_BLOCKS  ((size_t)W_TILES * 1024 / 256)   // 2048

// ======================= static fp16 scratch: TILED + PRE-SWIZZLED =======================
__device__ __align__(1024) unsigned char g_xh[(size_t)MDIM * KDIM * 2];              // 64 MB
__device__ __align__(1024) unsigned char g_wc[(size_t)NBATCH * NDIM * KDIM * 2];     // 128 MB

// ======================= small helpers =======================
__device__ __forceinline__ uint32_t h2_as_u32(__half2 h) {
    return *reinterpret_cast<uint32_t*>(&h);
}

__device__ __forceinline__ uint32_t smem_u32(const void* p) {
    uint32_t a;
    asm("{ .reg .u64 t; cvta.to.shared.u64 t, %1; cvt.u32.u64 %0, t; }" : "=r"(a) : "l"(p));
    return a;
}

#define SW128(o) ((o) ^ (((o) >> 3) & 0x70))

__device__ __forceinline__ void mbar_init(uint32_t bar, uint32_t cnt) {
    asm volatile("mbarrier.init.shared.b64 [%0], %1;" :: "r"(bar), "r"(cnt) : "memory");
}
__device__ __forceinline__ void mbar_arrive(uint32_t bar) {
    asm volatile("mbarrier.arrive.shared.b64 _, [%0];" :: "r"(bar) : "memory");
}
__device__ __forceinline__ void mbar_expect_tx(uint32_t bar, uint32_t bytes) {
    asm volatile("mbarrier.arrive.expect_tx.shared.b64 _, [%0], %1;" :: "r"(bar), "r"(bytes) : "memory");
}
__device__ __forceinline__ void mbar_wait(uint32_t bar, uint32_t parity) {
    asm volatile(
        "{\n\t"
        ".reg .pred P;\n\t"
        "WL_%=:\n\t"
        "mbarrier.try_wait.parity.acquire.cta.shared::cta.b64 P, [%0], %1, 0x989680;\n\t"
        "@P bra.uni WD_%=;\n\t"
        "bra.uni WL_%=;\n\t"
        "WD_%=:\n\t"
        "}"
        :: "r"(bar), "r"(parity) : "memory");
}
// 1D bulk async copy global->shared, completes via mbarrier tx (sm_90 baseline PTX)
__device__ __forceinline__ void bulk_g2s(uint32_t dst, const void* src, uint32_t bytes, uint32_t bar) {
    asm volatile(
        "cp.async.bulk.shared::cluster.global.mbarrier::complete_tx::bytes [%0], [%1], %2, [%3];"
        :: "r"(dst), "l"(src), "r"(bytes), "r"(bar) : "memory");
}

__device__ __forceinline__ void ldsm4(uint32_t* d, uint32_t addr) {
    asm volatile("ldmatrix.sync.aligned.m8n8.x4.shared.b16 {%0,%1,%2,%3}, [%4];"
                 : "=r"(d[0]), "=r"(d[1]), "=r"(d[2]), "=r"(d[3]) : "r"(addr));
}

__device__ __forceinline__ void mma16816(float* c, const uint32_t* a, uint32_t b0, uint32_t b1) {
    asm volatile(
        "mma.sync.aligned.m16n8k16.row.col.f32.f16.f16.f32 "
        "{%0,%1,%2,%3}, {%4,%5,%6,%7}, {%8,%9}, {%0,%1,%2,%3};"
        : "+f"(c[0]), "+f"(c[1]), "+f"(c[2]), "+f"(c[3])
        : "r"(a[0]), "r"(a[1]), "r"(a[2]), "r"(a[3]), "r"(b0), "r"(b1));
}

__device__ __forceinline__ void stg_cs_v2(float* p, float2 v) {
    asm volatile("st.global.cs.v2.f32 [%0], {%1, %2};" :: "l"(p), "f"(v.x), "f"(v.y) : "memory");
}

// ======================= fused pre-pass: convert + tile + swizzle (proven) =======================
__global__ void __launch_bounds__(256) pre_kernel(const float* __restrict__ x,
                                                  const float* __restrict__ w,
                                                  const float* __restrict__ g,
                                                  const float* __restrict__ lr) {
    const int tid = threadIdx.x;
    if (blockIdx.x < X_BLOCKS) {
        size_t cid = (size_t)blockIdx.x * 256 + tid;       // 16B chunk id
        size_t tileIdx = cid >> 10;                        // 1024 chunks per tile
        int t  = (int)(cid & 1023);
        int r  = t >> 3, cc = t & 7;
        int mb = (int)(tileIdx >> 4), kt = (int)(tileIdx & 15);
        const float* src = x + ((size_t)mb * 128 + r) * KDIM + kt * 64 + cc * 8;
        float4 v0 = *reinterpret_cast<const float4*>(src);
        float4 v1 = *reinterpret_cast<const float4*>(src + 4);
        uint4 o;
        o.x = h2_as_u32(__floats2half2_rn(v0.x, v0.y));
        o.y = h2_as_u32(__floats2half2_rn(v0.z, v0.w));
        o.z = h2_as_u32(__floats2half2_rn(v1.x, v1.y));
        o.w = h2_as_u32(__floats2half2_rn(v1.z, v1.w));
        *reinterpret_cast<uint4*>(g_xh + tileIdx * TILEB + SW128(r * 128 + cc * 16)) = o;
    } else {
        size_t cid = (size_t)(blockIdx.x - X_BLOCKS) * 256 + tid;
        size_t tileIdx = cid >> 10;                                  // 0..511
        int t  = (int)(cid & 1023);
        int r  = t >> 3, cc = t & 7;
        int nb = (int)(tileIdx >> 4), kt = (int)(tileIdx & 15);
        const size_t soff = ((size_t)nb * 128 + r) * KDIM + kt * 64 + cc * 8;
        float4 vw0 = *reinterpret_cast<const float4*>(w + soff);
        float4 vw1 = *reinterpret_cast<const float4*>(w + soff + 4);
        float4 vg0 = *reinterpret_cast<const float4*>(g + soff);
        float4 vg1 = *reinterpret_cast<const float4*>(g + soff + 4);
        const uint32_t swoff = SW128(r * 128 + cc * 16);
        #pragma unroll
        for (int b = 0; b < NBATCH; ++b) {
            float l = __ldg(lr + b);
            uint4 o;
            o.x = h2_as_u32(__floats2half2_rn(vw0.x - l * vg0.x, vw0.y - l * vg0.y));
            o.y = h2_as_u32(__floats2half2_rn(vw0.z - l * vg0.z, vw0.w - l * vg0.w));
            o.z = h2_as_u32(__floats2half2_rn(vw1.x - l * vg1.x, vw1.y - l * vg1.y));
            o.w = h2_as_u32(__floats2half2_rn(vw1.z - l * vg1.z, vw1.w - l * vg1.w));
            *reinterpret_cast<uint4*>(g_wc + ((size_t)b * W_TILES + tileIdx) * TILEB + swoff) = o;
        }
    }
}

// ======================= GEMM kernel =======================
// 128 threads = 4 warps (2x2), warp tile 64x64, mma m16n8k16.
// Cross-ktile software pipelining: at ks==3 the warp waits the NEXT stage's full
// barrier and primes the next ktile's ks=0 fragments, all hidden under the
// current mma blocks' tensor-pipe back-pressure. Math stream identical to champion.
__global__ void __launch_bounds__(128, 2) gemm_kernel(const float* __restrict__ bias,
                                                      const float* __restrict__ gbias,
                                                      const float* __restrict__ lr_arr,
                                                      float* __restrict__ out) {
    extern __shared__ char smem[];
    const uint32_t sb = smem_u32(smem);
    const int tid  = threadIdx.x;
    const int warp = tid >> 5, lane = tid & 31;
    const int warp_m = (warp & 1) * 64;
    const int warp_n = (warp >> 1) * 64;

    const int mb    = blockIdx.y;          // 0..255
    const int nb    = blockIdx.x;          // 0..31
    const int batch = mb >> 4;
    const int rowA0 = mb * BM;
    const int colB0 = nb * BN;

    const unsigned char* Abase = g_xh + (size_t)(mb * NKT) * TILEB;
    const unsigned char* Bbase = g_wc + ((size_t)batch * W_TILES + nb * NKT) * TILEB;

    const uint32_t full_b  = sb + OFF_FULL;
    const uint32_t empty_b = sb + OFF_EMPTY;

    if (tid == 0) {
        #pragma unroll
        for (int s = 0; s < STAGES; ++s) {
            mbar_init(full_b + s * 8, 1);
            mbar_init(empty_b + s * 8, 128);
        }
    }
    __syncthreads();

    // prologue: tid 0 fills all 3 stages
    if (tid == 0) {
        #pragma unroll
        for (int p = 0; p < STAGES; ++p) {
            const uint32_t dst = sb + SMEM_STAGE0 + p * STAGEB;
            mbar_expect_tx(full_b + p * 8, STAGEB);
            bulk_g2s(dst,         Abase + (size_t)p * TILEB, TILEB, full_b + p * 8);
            bulk_g2s(dst + TILEB, Bbase + (size_t)p * TILEB, TILEB, full_b + p * 8);
        }
    }

    // ldsm lane addressing (stage-relative, swizzled)
    const int a_row  = warp_m + (lane & 15);
    const int a_colb = (lane >> 4) * 16;
    const int b_row  = warp_n + ((lane >> 4) * 8 + (lane & 7));
    const int b_colb = ((lane >> 3) & 1) * 16;

    float acc[4][8][4];
    #pragma unroll
    for (int i = 0; i < 4; ++i)
        #pragma unroll
        for (int j = 0; j < 8; ++j)
            #pragma unroll
            for (int t = 0; t < 4; ++t) acc[i][j][t] = 0.0f;

    uint32_t afr[2][4][4], bfr[2][4][4];

    // initial: wait stage 0, prime ks=0 fragments into buffer 0
    mbar_wait(full_b + 0, 0);
    {
        const uint32_t Ab0 = sb + SMEM_STAGE0;
        const uint32_t Bb0 = Ab0 + TILEB;
        #pragma unroll
        for (int mf = 0; mf < 4; ++mf)
            ldsm4(afr[0][mf], Ab0 + SW128((a_row + mf * 16) * 128 + a_colb));
        #pragma unroll
        for (int np = 0; np < 4; ++np)
            ldsm4(bfr[0][np], Bb0 + SW128((b_row + np * 16) * 128 + b_colb));
    }

    for (int kt = 0; kt < NKT; ++kt) {
        const int s = kt % STAGES;
        const uint32_t Ab = sb + SMEM_STAGE0 + s * STAGEB;
        const uint32_t Bb = Ab + TILEB;

        #pragma unroll
        for (int ks = 0; ks < 4; ++ks) {
            const int cur = ks & 1, nxtb = cur ^ 1;
            if (ks < 3) {
                // prefetch next k-slice of the current stage
                const int kb = (ks + 1) * 32;
                #pragma unroll
                for (int mf = 0; mf < 4; ++mf)
                    ldsm4(afr[nxtb][mf], Ab + SW128((a_row + mf * 16) * 128 + kb + a_colb));
                #pragma unroll
                for (int np = 0; np < 4; ++np)
                    ldsm4(bfr[nxtb][np], Bb + SW128((b_row + np * 16) * 128 + kb + b_colb));
            } else if (kt + 1 < NKT) {
                // cross-ktile: wait next stage full, prime its ks=0 fragments.
                // Issued while ks=2/ks=3 mma still occupy the tensor pipe.
                const int s2 = (kt + 1) % STAGES;
                mbar_wait(full_b + s2 * 8, (uint32_t)(((kt + 1) / STAGES) & 1));
                const uint32_t Ab2 = sb + SMEM_STAGE0 + s2 * STAGEB;
                const uint32_t Bb2 = Ab2 + TILEB;
                #pragma unroll
                for (int mf = 0; mf < 4; ++mf)
                    ldsm4(afr[nxtb][mf], Ab2 + SW128((a_row + mf * 16) * 128 + a_colb));
                #pragma unroll
                for (int np = 0; np < 4; ++np)
                    ldsm4(bfr[nxtb][np], Bb2 + SW128((b_row + np * 16) * 128 + b_colb));
            }
            // 32 mma on current buffers
            #pragma unroll
            for (int mf = 0; mf < 4; ++mf) {
                #pragma unroll
                for (int np = 0; np < 4; ++np) {
                    mma16816(acc[mf][2 * np],     afr[cur][mf], bfr[cur][np][0], bfr[cur][np][1]);
                    mma16816(acc[mf][2 * np + 1], afr[cur][mf], bfr[cur][np][2], bfr[cur][np][3]);
                }
            }
        }

        // release stage; tid 0 refills it for kt+3 once everyone arrived
        mbar_arrive(empty_b + s * 8);
        const int nx = kt + STAGES;
        if (tid == 0 && nx < NKT) {
            mbar_wait(empty_b + s * 8, (uint32_t)((kt / STAGES) & 1));
            const uint32_t dst = sb + SMEM_STAGE0 + s * STAGEB;
            mbar_expect_tx(full_b + s * 8, STAGEB);
            bulk_g2s(dst,         Abase + (size_t)nx * TILEB, TILEB, full_b + s * 8);
            bulk_g2s(dst + TILEB, Bbase + (size_t)nx * TILEB, TILEB, full_b + s * 8);
        }
    }

    // ---------- epilogue (champion pattern; streaming stores) ----------
    __syncthreads();
    float* bias_s = reinterpret_cast<float*>(smem + SMEM_STAGE0);
    float* gb_s   = bias_s + BN;
    bias_s[tid] = bias[colB0 + tid];        // 128 threads == BN
    gb_s[tid]   = gbias[colB0 + tid];
    __syncthreads();

    const float lr = __ldg(lr_arr + batch);

    #pragma unroll
    for (int mf = 0; mf < 4; ++mf) {
        const int gr0 = rowA0 + warp_m + mf * 16 + (lane >> 2);
        #pragma unroll
        for (int nf = 0; nf < 8; ++nf) {
            const int cl = warp_n + nf * 8 + (lane & 3) * 2;
            const float bc0 = bias_s[cl]     - lr * gb_s[cl];
            const float bc1 = bias_s[cl + 1] - lr * gb_s[cl + 1];
            float2 v0 = make_float2(acc[mf][nf][0] + bc0, acc[mf][nf][1] + bc1);
            float2 v1 = make_float2(acc[mf][nf][2] + bc0, acc[mf][nf][3] + bc1);
            stg_cs_v2(out + (size_t)gr0 * NDIM + colB0 + cl,       v0);
            stg_cs_v2(out + (size_t)(gr0 + 8) * NDIM + colB0 + cl, v1);
        }
    }
}

// ======================= launch =======================
extern "C" void kernel_launch(void* const* d_in, const int* in_sizes, int n_in,
                              void* d_out, int out_size) {
    (void)in_sizes; (void)n_in; (void)out_size;
    const float* x    = (const float*)d_in[0];
    const float* w    = (const float*)d_in[1];
    const float* bias = (const float*)d_in[2];
    const float* g    = (const float*)d_in[3];
    const float* gb   = (const float*)d_in[4];
    const float* lr   = (const float*)d_in[5];
    float* out = (float*)d_out;

    static bool attr_set = false;
    if (!attr_set) {
        cudaFuncSetAttribute(gemm_kernel, cudaFuncAttributeMaxDynamicSharedMemorySize, SMEMB);
        attr_set = true;
    }

    pre_kernel<<<(unsigned)(X_BLOCKS + W_BLOCKS), 256>>>(x, w, g, lr);

    dim3 grid(NDIM / BN, MDIM / BM);   // (32, 256): N fastest for A-tile L2 reuse
    gemm_kernel<<<grid, 128, SMEMB>>>(bias, gb, lr, out);
}

// round 13
// speedup vs baseline: 1.1345x; 1.0439x over previous
#include <cuda_runtime.h>
#include <cuda_fp16.h>
#include <cstdint>

// ======================= problem constants =======================
#define MDIM 32768      // B*S = 16*2048
#define NDIM 4096       // out features
#define KDIM 1024       // in features
#define NBATCH 16

#define BM 128
#define BN 128
#define BK 64                 // halves per K-slab = one SW128 tile col-block
#define NKT (KDIM / BK)       // 16
#define STAGES 3

#define TILEB  16384                // one 128x64-half tile, swizzled, contiguous
#define STAGEB (2 * TILEB)          // A + B = 32768
#define SMEM_STAGE0 1024
#define SMEMB  (SMEM_STAGE0 + STAGES * STAGEB)   // 99328 -> 2 CTAs/SM

// barrier smem offsets
#define OFF_FULL  0      // 3 x 8B
#define OFF_EMPTY 64     // 3 x 8B

// pre-kernel grid split
#define X_TILES   (MDIM / BM * NKT)                // 4096 tiles
#define X_BLOCKS  ((size_t)X_TILES * 1024 / 256)   // 16384
#define W_TILES   (NDIM / BN * NKT)                // 512 tiles per batch
#define W_BLOCKS  ((size_t)W_TILES * 1024 / 256)   // 2048

// ======================= static fp16 scratch: TILED + PRE-SWIZZLED =======================
__device__ __align__(1024) unsigned char g_xh[(size_t)MDIM * KDIM * 2];              // 64 MB
__device__ __align__(1024) unsigned char g_wc[(size_t)NBATCH * NDIM * KDIM * 2];     // 128 MB

// ======================= small helpers =======================
__device__ __forceinline__ uint32_t h2_as_u32(__half2 h) {
    return *reinterpret_cast<uint32_t*>(&h);
}

__device__ __forceinline__ uint32_t smem_u32(const void* p) {
    uint32_t a;
    asm("{ .reg .u64 t; cvta.to.shared.u64 t, %1; cvt.u32.u64 %0, t; }" : "=r"(a) : "l"(p));
    return a;
}

#define SW128(o) ((o) ^ (((o) >> 3) & 0x70))

__device__ __forceinline__ void mbar_init(uint32_t bar, uint32_t cnt) {
    asm volatile("mbarrier.init.shared.b64 [%0], %1;" :: "r"(bar), "r"(cnt) : "memory");
}
__device__ __forceinline__ void mbar_arrive(uint32_t bar) {
    asm volatile("mbarrier.arrive.shared.b64 _, [%0];" :: "r"(bar) : "memory");
}
__device__ __forceinline__ void mbar_expect_tx(uint32_t bar, uint32_t bytes) {
    asm volatile("mbarrier.arrive.expect_tx.shared.b64 _, [%0], %1;" :: "r"(bar), "r"(bytes) : "memory");
}
__device__ __forceinline__ void mbar_wait(uint32_t bar, uint32_t parity) {
    asm volatile(
        "{\n\t"
        ".reg .pred P;\n\t"
        "WL_%=:\n\t"
        "mbarrier.try_wait.parity.acquire.cta.shared::cta.b64 P, [%0], %1, 0x989680;\n\t"
        "@P bra.uni WD_%=;\n\t"
        "bra.uni WL_%=;\n\t"
        "WD_%=:\n\t"
        "}"
        :: "r"(bar), "r"(parity) : "memory");
}
// 1D bulk async copy global->shared, completes via mbarrier tx (sm_90 baseline PTX)
__device__ __forceinline__ void bulk_g2s(uint32_t dst, const void* src, uint32_t bytes, uint32_t bar) {
    asm volatile(
        "cp.async.bulk.shared::cluster.global.mbarrier::complete_tx::bytes [%0], [%1], %2, [%3];"
        :: "r"(dst), "l"(src), "r"(bytes), "r"(bar) : "memory");
}

__device__ __forceinline__ void ldsm4(uint32_t* d, uint32_t addr) {
    asm volatile("ldmatrix.sync.aligned.m8n8.x4.shared.b16 {%0,%1,%2,%3}, [%4];"
                 : "=r"(d[0]), "=r"(d[1]), "=r"(d[2]), "=r"(d[3]) : "r"(addr));
}

__device__ __forceinline__ void mma16816(float* c, const uint32_t* a, uint32_t b0, uint32_t b1) {
    asm volatile(
        "mma.sync.aligned.m16n8k16.row.col.f32.f16.f16.f32 "
        "{%0,%1,%2,%3}, {%4,%5,%6,%7}, {%8,%9}, {%0,%1,%2,%3};"
        : "+f"(c[0]), "+f"(c[1]), "+f"(c[2]), "+f"(c[3])
        : "r"(a[0]), "r"(a[1]), "r"(a[2]), "r"(a[3]), "r"(b0), "r"(b1));
}

__device__ __forceinline__ void stg_cs_v2(float* p, float2 v) {
    asm volatile("st.global.cs.v2.f32 [%0], {%1, %2};" :: "l"(p), "f"(v.x), "f"(v.y) : "memory");
}

// ======================= fused pre-pass: convert + tile + swizzle (proven) =======================
__global__ void __launch_bounds__(256) pre_kernel(const float* __restrict__ x,
                                                  const float* __restrict__ w,
                                                  const float* __restrict__ g,
                                                  const float* __restrict__ lr) {
    const int tid = threadIdx.x;
    if (blockIdx.x < X_BLOCKS) {
        size_t cid = (size_t)blockIdx.x * 256 + tid;       // 16B chunk id
        size_t tileIdx = cid >> 10;                        // 1024 chunks per tile
        int t  = (int)(cid & 1023);
        int r  = t >> 3, cc = t & 7;
        int mb = (int)(tileIdx >> 4), kt = (int)(tileIdx & 15);
        const float* src = x + ((size_t)mb * 128 + r) * KDIM + kt * 64 + cc * 8;
        float4 v0 = *reinterpret_cast<const float4*>(src);
        float4 v1 = *reinterpret_cast<const float4*>(src + 4);
        uint4 o;
        o.x = h2_as_u32(__floats2half2_rn(v0.x, v0.y));
        o.y = h2_as_u32(__floats2half2_rn(v0.z, v0.w));
        o.z = h2_as_u32(__floats2half2_rn(v1.x, v1.y));
        o.w = h2_as_u32(__floats2half2_rn(v1.z, v1.w));
        *reinterpret_cast<uint4*>(g_xh + tileIdx * TILEB + SW128(r * 128 + cc * 16)) = o;
    } else {
        size_t cid = (size_t)(blockIdx.x - X_BLOCKS) * 256 + tid;
        size_t tileIdx = cid >> 10;                                  // 0..511
        int t  = (int)(cid & 1023);
        int r  = t >> 3, cc = t & 7;
        int nb = (int)(tileIdx >> 4), kt = (int)(tileIdx & 15);
        const size_t soff = ((size_t)nb * 128 + r) * KDIM + kt * 64 + cc * 8;
        float4 vw0 = *reinterpret_cast<const float4*>(w + soff);
        float4 vw1 = *reinterpret_cast<const float4*>(w + soff + 4);
        float4 vg0 = *reinterpret_cast<const float4*>(g + soff);
        float4 vg1 = *reinterpret_cast<const float4*>(g + soff + 4);
        const uint32_t swoff = SW128(r * 128 + cc * 16);
        #pragma unroll
        for (int b = 0; b < NBATCH; ++b) {
            float l = __ldg(lr + b);
            uint4 o;
            o.x = h2_as_u32(__floats2half2_rn(vw0.x - l * vg0.x, vw0.y - l * vg0.y));
            o.y = h2_as_u32(__floats2half2_rn(vw0.z - l * vg0.z, vw0.w - l * vg0.w));
            o.z = h2_as_u32(__floats2half2_rn(vw1.x - l * vg1.x, vw1.y - l * vg1.y));
            o.w = h2_as_u32(__floats2half2_rn(vw1.z - l * vg1.z, vw1.w - l * vg1.w));
            *reinterpret_cast<uint4*>(g_wc + ((size_t)b * W_TILES + tileIdx) * TILEB + swoff) = o;
        }
    }
}

// ======================= GEMM kernel =======================
// 128 threads = 4 warps (2x2), warp tile 64x64, mma m16n8k16.
// R12 cross-ktile pipelining + R13: EARLY empty-arrive (after the ks==2 ldsm batch,
// the last smem reads of the stage) so tid 0's refill wait stops tail-syncing the CTA.
__global__ void __launch_bounds__(128, 2) gemm_kernel(const float* __restrict__ bias,
                                                      const float* __restrict__ gbias,
                                                      const float* __restrict__ lr_arr,
                                                      float* __restrict__ out) {
    extern __shared__ char smem[];
    const uint32_t sb = smem_u32(smem);
    const int tid  = threadIdx.x;
    const int warp = tid >> 5, lane = tid & 31;
    const int warp_m = (warp & 1) * 64;
    const int warp_n = (warp >> 1) * 64;

    const int mb    = blockIdx.y;          // 0..255
    const int nb    = blockIdx.x;          // 0..31
    const int batch = mb >> 4;
    const int rowA0 = mb * BM;
    const int colB0 = nb * BN;

    const unsigned char* Abase = g_xh + (size_t)(mb * NKT) * TILEB;
    const unsigned char* Bbase = g_wc + ((size_t)batch * W_TILES + nb * NKT) * TILEB;

    const uint32_t full_b  = sb + OFF_FULL;
    const uint32_t empty_b = sb + OFF_EMPTY;

    if (tid == 0) {
        #pragma unroll
        for (int s = 0; s < STAGES; ++s) {
            mbar_init(full_b + s * 8, 1);
            mbar_init(empty_b + s * 8, 128);
        }
    }
    __syncthreads();

    // prologue: tid 0 fills all 3 stages
    if (tid == 0) {
        #pragma unroll
        for (int p = 0; p < STAGES; ++p) {
            const uint32_t dst = sb + SMEM_STAGE0 + p * STAGEB;
            mbar_expect_tx(full_b + p * 8, STAGEB);
            bulk_g2s(dst,         Abase + (size_t)p * TILEB, TILEB, full_b + p * 8);
            bulk_g2s(dst + TILEB, Bbase + (size_t)p * TILEB, TILEB, full_b + p * 8);
        }
    }

    // ldsm lane addressing (stage-relative, swizzled)
    const int a_row  = warp_m + (lane & 15);
    const int a_colb = (lane >> 4) * 16;
    const int b_row  = warp_n + ((lane >> 4) * 8 + (lane & 7));
    const int b_colb = ((lane >> 3) & 1) * 16;

    float acc[4][8][4];
    #pragma unroll
    for (int i = 0; i < 4; ++i)
        #pragma unroll
        for (int j = 0; j < 8; ++j)
            #pragma unroll
            for (int t = 0; t < 4; ++t) acc[i][j][t] = 0.0f;

    uint32_t afr[2][4][4], bfr[2][4][4];

    // initial: wait stage 0, prime ks=0 fragments into buffer 0
    mbar_wait(full_b + 0, 0);
    {
        const uint32_t Ab0 = sb + SMEM_STAGE0;
        const uint32_t Bb0 = Ab0 + TILEB;
        #pragma unroll
        for (int mf = 0; mf < 4; ++mf)
            ldsm4(afr[0][mf], Ab0 + SW128((a_row + mf * 16) * 128 + a_colb));
        #pragma unroll
        for (int np = 0; np < 4; ++np)
            ldsm4(bfr[0][np], Bb0 + SW128((b_row + np * 16) * 128 + b_colb));
    }

    for (int kt = 0; kt < NKT; ++kt) {
        const int s = kt % STAGES;
        const uint32_t Ab = sb + SMEM_STAGE0 + s * STAGEB;
        const uint32_t Bb = Ab + TILEB;

        #pragma unroll
        for (int ks = 0; ks < 4; ++ks) {
            const int cur = ks & 1, nxtb = cur ^ 1;
            if (ks < 3) {
                // prefetch next k-slice of the current stage
                const int kb = (ks + 1) * 32;
                #pragma unroll
                for (int mf = 0; mf < 4; ++mf)
                    ldsm4(afr[nxtb][mf], Ab + SW128((a_row + mf * 16) * 128 + kb + a_colb));
                #pragma unroll
                for (int np = 0; np < 4; ++np)
                    ldsm4(bfr[nxtb][np], Bb + SW128((b_row + np * 16) * 128 + kb + b_colb));
                // ks==2 issued the LAST smem reads of stage s -> release it now.
                // (ks==3's mma consumes registers; its ldsm targets the next stage.)
                if (ks == 2) mbar_arrive(empty_b + s * 8);
            } else if (kt + 1 < NKT) {
                // cross-ktile: wait next stage full, prime its ks=0 fragments.
                const int s2 = (kt + 1) % STAGES;
                mbar_wait(full_b + s2 * 8, (uint32_t)(((kt + 1) / STAGES) & 1));
                const uint32_t Ab2 = sb + SMEM_STAGE0 + s2 * STAGEB;
                const uint32_t Bb2 = Ab2 + TILEB;
                #pragma unroll
                for (int mf = 0; mf < 4; ++mf)
                    ldsm4(afr[nxtb][mf], Ab2 + SW128((a_row + mf * 16) * 128 + a_colb));
                #pragma unroll
                for (int np = 0; np < 4; ++np)
                    ldsm4(bfr[nxtb][np], Bb2 + SW128((b_row + np * 16) * 128 + b_colb));
            }
            // 32 mma on current buffers
            #pragma unroll
            for (int mf = 0; mf < 4; ++mf) {
                #pragma unroll
                for (int np = 0; np < 4; ++np) {
                    mma16816(acc[mf][2 * np],     afr[cur][mf], bfr[cur][np][0], bfr[cur][np][1]);
                    mma16816(acc[mf][2 * np + 1], afr[cur][mf], bfr[cur][np][2], bfr[cur][np][3]);
                }
            }
        }

        // tid 0 refills slot s for kt+3 (empty arrivals happened back at ks==2)
        const int nx = kt + STAGES;
        if (tid == 0 && nx < NKT) {
            mbar_wait(empty_b + s * 8, (uint32_t)((kt / STAGES) & 1));
            const uint32_t dst = sb + SMEM_STAGE0 + s * STAGEB;
            mbar_expect_tx(full_b + s * 8, STAGEB);
            bulk_g2s(dst,         Abase + (size_t)nx * TILEB, TILEB, full_b + s * 8);
            bulk_g2s(dst + TILEB, Bbase + (size_t)nx * TILEB, TILEB, full_b + s * 8);
        }
    }

    // ---------- epilogue: direct L2-hot bias loads, no block sync ----------
    const float lr = __ldg(lr_arr + batch);

    #pragma unroll
    for (int mf = 0; mf < 4; ++mf) {
        const int gr0 = rowA0 + warp_m + mf * 16 + (lane >> 2);
        #pragma unroll
        for (int nf = 0; nf < 8; ++nf) {
            const int cl = colB0 + warp_n + nf * 8 + (lane & 3) * 2;
            const float bc0 = __ldg(bias + cl)     - lr * __ldg(gbias + cl);
            const float bc1 = __ldg(bias + cl + 1) - lr * __ldg(gbias + cl + 1);
            float2 v0 = make_float2(acc[mf][nf][0] + bc0, acc[mf][nf][1] + bc1);
            float2 v1 = make_float2(acc[mf][nf][2] + bc0, acc[mf][nf][3] + bc1);
            stg_cs_v2(out + (size_t)gr0 * NDIM + cl,       v0);
            stg_cs_v2(out + (size_t)(gr0 + 8) * NDIM + cl, v1);
        }
    }
}

// ======================= launch =======================
extern "C" void kernel_launch(void* const* d_in, const int* in_sizes, int n_in,
                              void* d_out, int out_size) {
    (void)in_sizes; (void)n_in; (void)out_size;
    const float* x    = (const float*)d_in[0];
    const float* w    = (const float*)d_in[1];
    const float* bias = (const float*)d_in[2];
    const float* g    = (const float*)d_in[3];
    const float* gb   = (const float*)d_in[4];
    const float* lr   = (const float*)d_in[5];
    float* out = (float*)d_out;

    static bool attr_set = false;
    if (!attr_set) {
        cudaFuncSetAttribute(gemm_kernel, cudaFuncAttributeMaxDynamicSharedMemorySize, SMEMB);
        attr_set = true;
    }

    pre_kernel<<<(unsigned)(X_BLOCKS + W_BLOCKS), 256>>>(x, w, g, lr);

    dim3 grid(NDIM / BN, MDIM / BM);   // (32, 256): N fastest for A-tile L2 reuse
    gemm_kernel<<<grid, 128, SMEMB>>>(bias, gb, lr, out);
}